// round 13
// baseline (speedup 1.0000x reference)
#include <cuda_runtime.h>
#include <cuda_bf16.h>

#define NA   400000
#define NG   64
#define CAP  32768
#define TOPK 10
#define TBS  256
#define MAXIN 8

// Inputs passed by value (capture-safe, no host-side device reads needed).
struct Bind { const void* p[MAXIN]; int sz[MAXIN]; int n; };

// Content-selected input pointers (published by k_select, read by later kernels).
__device__ const float*  sel_sc;   // pd_scores  [NA]
__device__ const float4* sel_pb;   // pd_bboxes  [NA]
__device__ const float2* sel_an;   // anc_points [NA]
__device__ const float4* sel_gt;   // gt_bboxes  [NG]

// Scratch (device globals: no allocations allowed anywhere).
__device__ int   g_count[NG];
__device__ float g_thresh[NG];
__device__ float g_val[NG * CAP];
__device__ int   g_anc[NG * CAP];
__device__ int   g_best[NA];
__device__ int   g_fg[NA];

// K0: classify every input buffer by CONTENT (robust to ordering, extra inputs,
// and duplicate sizes), and reset the per-GT counters for this replay.
__global__ void k_select(Bind b) {
    const int tid = threadIdx.x;
    if (tid < NG) g_count[tid] = 0;
    if (tid != 0) return;

    const float*  sc = nullptr;
    const float4* pb = nullptr;
    const float2* an = nullptr;
    const float4* gt = nullptr;

    for (int i = 0; i < b.n; ++i) {
        const int s = b.sz[i];
        const float* f = (const float*)b.p[i];
        if (s == NG * 4) {                       // gt_bboxes: 64 valid boxes in [0,640]
            bool ok = true; float mx = 0.f;
            for (int g = 0; g < NG; ++g) {
                float x0 = f[4*g], y0 = f[4*g+1], x1 = f[4*g+2], y1 = f[4*g+3];
                if (!(x0 >= -1.f && y0 >= -1.f && x1 <= 642.f && y1 <= 642.f &&
                      x1 > x0 && y1 > y0)) { ok = false; break; }
                mx = fmaxf(mx, x1);
            }
            if (ok && mx > 50.f && !gt) gt = (const float4*)f;
        } else if (s == NA * 4) {                // pd_bboxes: unique size
            if (!pb) pb = (const float4*)f;
        } else if (s == NA * 2) {                // anc_points: [0,640], large values present
            bool ok = true; float mx = 0.f;
            for (int j = 0; j < 512; ++j) {
                float v = f[j];
                if (!(v >= 0.f && v <= 642.f)) { ok = false; break; }
                mx = fmaxf(mx, v);
            }
            if (ok && mx > 100.f && !an) an = (const float2*)f;
        } else if (s == NA) {                    // pd_scores: (0,1)
            bool ok = true; float mx = 0.f;
            for (int j = 0; j < 512; ++j) {
                float v = f[j];
                if (!(v >= 0.f && v <= 1.00001f)) { ok = false; break; }
                mx = fmaxf(mx, v);
            }
            if (ok && mx > 0.5f && !sc) sc = f;
        }
    }
    // Fallback: first size match if a content check rejected everything.
    for (int i = 0; i < b.n; ++i) {
        const int s = b.sz[i];
        if (s == NA     && !sc) sc = (const float*)b.p[i];
        if (s == NA * 4 && !pb) pb = (const float4*)b.p[i];
        if (s == NA * 2 && !an) an = (const float2*)b.p[i];
        if (s == NG * 4 && !gt) gt = (const float4*)b.p[i];
    }
    sel_sc = sc; sel_pb = pb; sel_an = an; sel_gt = gt;
}

// K1: main pass. One thread per anchor: 64-bit in-box mask via smem-broadcast
// compares, then sparse IoU/metric only on set bits (~0.8 per anchor).
__global__ void __launch_bounds__(TBS) k_main() {
    __shared__ float4 s_gt[NG];
    __shared__ float  s_area[NG];
    const int tid = threadIdx.x;
    if (tid < NG) {
        float4 bx = sel_gt[tid];
        s_gt[tid]   = bx;
        s_area[tid] = (bx.z - bx.x) * (bx.w - bx.y);
    }
    __syncthreads();

    const int a = blockIdx.x * blockDim.x + tid;
    if (a >= NA) return;

    const float2 p   = sel_an[a];
    const float4 pbx = sel_pb[a];
    const float  area1 = (pbx.z - pbx.x) * (pbx.w - pbx.y);
    const float  s0 = sel_sc[a];          // NUM_CLASSES == 1 -> class 0 for every gt

    unsigned long long mask = 0ull;
#pragma unroll
    for (int g = 0; g < NG; ++g) {
        float4 bx = s_gt[g];
        bool in = (p.x >= bx.x) && (p.x <= bx.z) && (p.y >= bx.y) && (p.y <= bx.w);
        if (in) mask |= (1ull << g);
    }

    float best = 0.f;
    int bestg = 0;                         // argmax of an all-zero row -> 0
    while (mask) {
        const int g = __ffsll((long long)mask) - 1;   // ascending g: first-max tie rule
        mask &= mask - 1ull;
        const float4 bx = s_gt[g];
        float lx = fmaxf(pbx.x, bx.x);
        float ly = fmaxf(pbx.y, bx.y);
        float rx = fminf(pbx.z, bx.z);
        float ry = fminf(pbx.w, bx.w);
        float w  = fmaxf(rx - lx, 0.f);
        float h  = fmaxf(ry - ly, 0.f);
        float inter = w * h;
        float iou = inter / (area1 + s_area[g] - inter);
        float i2  = iou * iou;
        float v   = s0 * (i2 * i2 * i2);   // cls^1 * iou^6
        if (v > best) { best = v; bestg = g; }
        if (v > 0.f) {
            int pos = atomicAdd(&g_count[g], 1);
            if (pos < CAP) {
                g_val[g * CAP + pos] = v;
                g_anc[g * CAP + pos] = a;
            }
        }
    }
    g_best[a] = bestg;
    g_fg[a]   = 0;                         // reset for K3 (graph replays reuse globals)
}

// K2: one block per GT -> 10th-largest candidate value becomes the threshold.
__global__ void __launch_bounds__(TBS) k_thresh() {
    const int g   = blockIdx.x;
    const int c   = min(g_count[g], CAP);
    const int tid = threadIdx.x;

    float t[TOPK];
#pragma unroll
    for (int i = 0; i < TOPK; ++i) t[i] = 0.f;

    for (int i = tid; i < c; i += TBS) {
        float v = g_val[g * CAP + i];
        if (v > t[0]) {
            t[0] = v;
#pragma unroll
            for (int k = 0; k < TOPK - 1; ++k) {
                if (t[k] > t[k + 1]) { float tmp = t[k]; t[k] = t[k + 1]; t[k + 1] = tmp; }
                else break;
            }
        }
    }

    __shared__ float sv[TBS * TOPK];
#pragma unroll
    for (int i = 0; i < TOPK; ++i) sv[tid * TOPK + i] = t[i];
    __syncthreads();

    for (int stride = TBS / 2; stride >= 1; stride >>= 1) {
        if (tid < stride) {
            float o[TOPK];
#pragma unroll
            for (int i = 0; i < TOPK; ++i) o[i] = sv[(tid + stride) * TOPK + i];
            float m[TOPK];
            int ti = TOPK - 1, oi = TOPK - 1;
#pragma unroll
            for (int k = TOPK - 1; k >= 0; --k) {
                float tv = (ti >= 0) ? t[ti] : -1.f;
                float ov = (oi >= 0) ? o[oi] : -1.f;
                if (tv >= ov) { m[k] = tv; --ti; }
                else          { m[k] = ov; --oi; }
            }
#pragma unroll
            for (int i = 0; i < TOPK; ++i) { t[i] = m[i]; sv[tid * TOPK + i] = m[i]; }
        }
        __syncthreads();
    }
    if (tid == 0) g_thresh[g] = t[0];      // 10th largest (0 if fewer than 10 positives)
}

// K3: mark fg anchors (all stored candidates are > 0, so >= thresh is the top-k set).
__global__ void __launch_bounds__(TBS) k_mark() {
    const int g = blockIdx.y;
    const int c = min(g_count[g], CAP);
    const float th = g_thresh[g];
    for (int i = blockIdx.x * blockDim.x + threadIdx.x; i < c;
         i += gridDim.x * blockDim.x) {
        if (g_val[g * CAP + i] >= th) g_fg[g_anc[g * CAP + i]] = 1;
    }
}

// K4: FLOAT32 output (the harness compares with a 1e-3 relative-error tolerance
// => single promoted float32 output dtype). out[0..A) = fg_mask as 0.0/1.0,
// out[A..2A) = assigned_gt_idx as float. Integer writes here read back as
// denormals (~1e-45 == 0) under a float comparator — the exact-1.0 failure
// signature of all previous rounds.
__global__ void __launch_bounds__(TBS) k_final(float* __restrict__ out, int write_idx) {
    const int a = blockIdx.x * blockDim.x + threadIdx.x;
    if (a >= NA) return;
    const int fg = g_fg[a];
    out[a] = fg ? 1.0f : 0.0f;
    if (write_idx) out[NA + a] = (float)(fg ? g_best[a] : 0);
}

extern "C" void kernel_launch(void* const* d_in, const int* in_sizes, int n_in,
                              void* d_out, int out_size) {
    Bind b;
    b.n = (n_in < MAXIN) ? n_in : MAXIN;
    for (int i = 0; i < b.n; ++i) { b.p[i] = d_in[i]; b.sz[i] = in_sizes[i]; }

    const int write_idx = (out_size >= 2 * NA) ? 1 : 0;

    k_select<<<1, 64>>>(b);
    k_main  <<<(NA + TBS - 1) / TBS, TBS>>>();
    k_thresh<<<NG, TBS>>>();
    k_mark  <<<dim3(8, NG), TBS>>>();
    k_final <<<(NA + TBS - 1) / TBS, TBS>>>((float*)d_out, write_idx);
}

// round 14
// speedup vs baseline: 1.2717x; 1.2717x over previous
#include <cuda_runtime.h>
#include <cuda_bf16.h>

#define NA   400000
#define NG   64
#define CAP  32768
#define TOPK 10
#define TBS  256

// Scratch (device globals: no allocations allowed anywhere).
__device__ int   g_count[NG];
__device__ float g_thresh[NG];
__device__ float g_val[NG * CAP];
__device__ int   g_anc[NG * CAP];
__device__ int   g_best[NA];
__device__ int   g_fg[NA];

// K0: reset per-GT candidate counters (graph replays reuse globals).
__global__ void k_zero() {
    if (threadIdx.x < NG) g_count[threadIdx.x] = 0;
}

// K1: main pass. One thread per anchor: 64-bit in-box mask via smem-broadcast
// compares, then sparse IoU/metric only on set bits (~0.8 per anchor).
__global__ void __launch_bounds__(TBS) k_main(
    const float*  __restrict__ scores,   // [NA]      (NUM_CLASSES == 1)
    const float4* __restrict__ pboxes,   // [NA]      (x0,y0,x1,y1)
    const float2* __restrict__ anc,      // [NA]      (x,y)
    const float4* __restrict__ gtb)      // [NG]      (x0,y0,x1,y1)
{
    __shared__ float4 s_gt[NG];
    __shared__ float  s_area[NG];
    const int tid = threadIdx.x;
    if (tid < NG) {
        float4 bx = gtb[tid];
        s_gt[tid]   = bx;
        s_area[tid] = (bx.z - bx.x) * (bx.w - bx.y);
    }
    __syncthreads();

    const int a = blockIdx.x * blockDim.x + tid;
    if (a >= NA) return;

    const float2 p   = anc[a];
    const float4 pbx = pboxes[a];
    const float  area1 = (pbx.z - pbx.x) * (pbx.w - pbx.y);
    const float  s0 = scores[a];

    unsigned long long mask = 0ull;
#pragma unroll
    for (int g = 0; g < NG; ++g) {
        float4 bx = s_gt[g];
        bool in = (p.x >= bx.x) && (p.x <= bx.z) && (p.y >= bx.y) && (p.y <= bx.w);
        if (in) mask |= (1ull << g);
    }

    float best = 0.f;
    int bestg = 0;                         // argmax of an all-zero row -> 0
    while (mask) {
        const int g = __ffsll((long long)mask) - 1;   // ascending g: first-max tie rule
        mask &= mask - 1ull;
        const float4 bx = s_gt[g];
        float lx = fmaxf(pbx.x, bx.x);
        float ly = fmaxf(pbx.y, bx.y);
        float rx = fminf(pbx.z, bx.z);
        float ry = fminf(pbx.w, bx.w);
        float w  = fmaxf(rx - lx, 0.f);
        float h  = fmaxf(ry - ly, 0.f);
        float inter = w * h;
        float iou = inter / (area1 + s_area[g] - inter);
        float i2  = iou * iou;
        float v   = s0 * (i2 * i2 * i2);   // cls^1 * iou^6
        if (v > best) { best = v; bestg = g; }
        if (v > 0.f) {
            int pos = atomicAdd(&g_count[g], 1);
            if (pos < CAP) {
                g_val[g * CAP + pos] = v;
                g_anc[g * CAP + pos] = a;
            }
        }
    }
    g_best[a] = bestg;
    g_fg[a]   = 0;                         // reset for K3
}

// K2: one block per GT -> 10th-largest candidate value becomes the threshold.
__global__ void __launch_bounds__(TBS) k_thresh() {
    const int g   = blockIdx.x;
    const int c   = min(g_count[g], CAP);
    const int tid = threadIdx.x;

    float t[TOPK];
#pragma unroll
    for (int i = 0; i < TOPK; ++i) t[i] = 0.f;

    for (int i = tid; i < c; i += TBS) {
        float v = g_val[g * CAP + i];
        if (v > t[0]) {
            t[0] = v;
#pragma unroll
            for (int k = 0; k < TOPK - 1; ++k) {
                if (t[k] > t[k + 1]) { float tmp = t[k]; t[k] = t[k + 1]; t[k + 1] = tmp; }
                else break;
            }
        }
    }

    __shared__ float sv[TBS * TOPK];
#pragma unroll
    for (int i = 0; i < TOPK; ++i) sv[tid * TOPK + i] = t[i];
    __syncthreads();

    for (int stride = TBS / 2; stride >= 1; stride >>= 1) {
        if (tid < stride) {
            float o[TOPK];
#pragma unroll
            for (int i = 0; i < TOPK; ++i) o[i] = sv[(tid + stride) * TOPK + i];
            float m[TOPK];
            int ti = TOPK - 1, oi = TOPK - 1;
#pragma unroll
            for (int k = TOPK - 1; k >= 0; --k) {
                float tv = (ti >= 0) ? t[ti] : -1.f;
                float ov = (oi >= 0) ? o[oi] : -1.f;
                if (tv >= ov) { m[k] = tv; --ti; }
                else          { m[k] = ov; --oi; }
            }
#pragma unroll
            for (int i = 0; i < TOPK; ++i) { t[i] = m[i]; sv[tid * TOPK + i] = m[i]; }
        }
        __syncthreads();
    }
    if (tid == 0) g_thresh[g] = t[0];      // 10th largest (0 if fewer than 10 positives)
}

// K3: mark fg anchors (all stored candidates are > 0, so >= thresh is the top-k set).
__global__ void __launch_bounds__(TBS) k_mark() {
    const int g = blockIdx.y;
    const int c = min(g_count[g], CAP);
    const float th = g_thresh[g];
    for (int i = blockIdx.x * blockDim.x + threadIdx.x; i < c;
         i += gridDim.x * blockDim.x) {
        if (g_val[g * CAP + i] >= th) g_fg[g_anc[g * CAP + i]] = 1;
    }
}

// K4: float32 output. out[0..A) = fg_mask as 0.0/1.0, out[A..2A) = argmax idx.
__global__ void __launch_bounds__(TBS) k_final(float* __restrict__ out, int write_idx) {
    const int a = blockIdx.x * blockDim.x + threadIdx.x;
    if (a >= NA) return;
    const int fg = g_fg[a];
    out[a] = fg ? 1.0f : 0.0f;
    if (write_idx) out[NA + a] = (float)(fg ? g_best[a] : 0);
}

extern "C" void kernel_launch(void* const* d_in, const int* in_sizes, int n_in,
                              void* d_out, int out_size) {
    // Bind inputs BY ELEMENT COUNT on the host — the five sizes are pairwise
    // distinct (400000 / 1600000 / 800000 / 64 / 256), so this is ordering-proof
    // and costs zero device work (the 246us run proved binding was never the
    // failure; the single-threaded device-side sniffer was pure overhead).
    const float*  scores = nullptr;
    const float4* pboxes = nullptr;
    const float2* anc    = nullptr;
    const float4* gtb    = nullptr;
    for (int i = 0; i < n_in; ++i) {
        switch (in_sizes[i]) {
            case NA:     scores = (const float*)d_in[i];  break;
            case NA * 4: pboxes = (const float4*)d_in[i]; break;
            case NA * 2: anc    = (const float2*)d_in[i]; break;
            case NG * 4: gtb    = (const float4*)d_in[i]; break;
            default: break;   // gt_labels (NG) unused: NUM_CLASSES == 1
        }
    }
    const int write_idx = (out_size >= 2 * NA) ? 1 : 0;

    k_zero  <<<1, 64>>>();
    k_main  <<<(NA + TBS - 1) / TBS, TBS>>>(scores, pboxes, anc, gtb);
    k_thresh<<<NG, TBS>>>();
    k_mark  <<<dim3(8, NG), TBS>>>();
    k_final <<<(NA + TBS - 1) / TBS, TBS>>>((float*)d_out, write_idx);
}

// round 15
// speedup vs baseline: 1.2752x; 1.0028x over previous
#include <cuda_runtime.h>
#include <cuda_bf16.h>

#define NA   400000
#define NG   64
#define CAP  32768
#define TOPK 10
#define TBS  256

// Scratch (device globals: no allocations allowed anywhere).
__device__ int   g_count[NG];
__device__ float g_thresh[NG];
__device__ float g_val[NG * CAP];
__device__ int   g_anc[NG * CAP];
__device__ int   g_best[NA];
__device__ int   g_fg[NA];

// K0: reset per-GT candidate counters (graph replays reuse globals).
__global__ void k_zero() {
    if (threadIdx.x < NG) g_count[threadIdx.x] = 0;
}

// K1: main pass. One thread per anchor: 64-bit in-box mask via smem-broadcast
// compares, then sparse IoU/metric only on set bits (~0.8 per anchor).
__global__ void __launch_bounds__(TBS) k_main(
    const float*  __restrict__ scores,   // [NA]      (NUM_CLASSES == 1)
    const float4* __restrict__ pboxes,   // [NA]      (x0,y0,x1,y1)
    const float2* __restrict__ anc,      // [NA]      (x,y)
    const float4* __restrict__ gtb)      // [NG]      (x0,y0,x1,y1)
{
    __shared__ float4 s_gt[NG];
    __shared__ float  s_area[NG];
    const int tid = threadIdx.x;
    if (tid < NG) {
        float4 bx = gtb[tid];
        s_gt[tid]   = bx;
        s_area[tid] = (bx.z - bx.x) * (bx.w - bx.y);
    }
    __syncthreads();

    const int a = blockIdx.x * blockDim.x + tid;
    if (a >= NA) return;

    const float2 p   = anc[a];
    const float4 pbx = pboxes[a];
    const float  area1 = (pbx.z - pbx.x) * (pbx.w - pbx.y);
    const float  s0 = scores[a];

    unsigned long long mask = 0ull;
#pragma unroll
    for (int g = 0; g < NG; ++g) {
        float4 bx = s_gt[g];
        bool in = (p.x >= bx.x) && (p.x <= bx.z) && (p.y >= bx.y) && (p.y <= bx.w);
        if (in) mask |= (1ull << g);
    }

    float best = 0.f;
    int bestg = 0;                         // argmax of an all-zero row -> 0
    while (mask) {
        const int g = __ffsll((long long)mask) - 1;   // ascending g: first-max tie rule
        mask &= mask - 1ull;
        const float4 bx = s_gt[g];
        float lx = fmaxf(pbx.x, bx.x);
        float ly = fmaxf(pbx.y, bx.y);
        float rx = fminf(pbx.z, bx.z);
        float ry = fminf(pbx.w, bx.w);
        float w  = fmaxf(rx - lx, 0.f);
        float h  = fmaxf(ry - ly, 0.f);
        float inter = w * h;
        float iou = inter / (area1 + s_area[g] - inter);
        float i2  = iou * iou;
        float v   = s0 * (i2 * i2 * i2);   // cls^1 * iou^6
        if (v > best) { best = v; bestg = g; }
        if (v > 0.f) {
            int pos = atomicAdd(&g_count[g], 1);
            if (pos < CAP) {
                g_val[g * CAP + pos] = v;
                g_anc[g * CAP + pos] = a;
            }
        }
    }
    g_best[a] = bestg;
    g_fg[a]   = 0;                         // reset for K3
}

// K2: one block per GT -> 10th-largest candidate value becomes the threshold.
__global__ void __launch_bounds__(TBS) k_thresh() {
    const int g   = blockIdx.x;
    const int c   = min(g_count[g], CAP);
    const int tid = threadIdx.x;

    float t[TOPK];
#pragma unroll
    for (int i = 0; i < TOPK; ++i) t[i] = 0.f;

    for (int i = tid; i < c; i += TBS) {
        float v = g_val[g * CAP + i];
        if (v > t[0]) {
            t[0] = v;
#pragma unroll
            for (int k = 0; k < TOPK - 1; ++k) {
                if (t[k] > t[k + 1]) { float tmp = t[k]; t[k] = t[k + 1]; t[k + 1] = tmp; }
                else break;
            }
        }
    }

    __shared__ float sv[TBS * TOPK];
#pragma unroll
    for (int i = 0; i < TOPK; ++i) sv[tid * TOPK + i] = t[i];
    __syncthreads();

    for (int stride = TBS / 2; stride >= 1; stride >>= 1) {
        if (tid < stride) {
            float o[TOPK];
#pragma unroll
            for (int i = 0; i < TOPK; ++i) o[i] = sv[(tid + stride) * TOPK + i];
            float m[TOPK];
            int ti = TOPK - 1, oi = TOPK - 1;
#pragma unroll
            for (int k = TOPK - 1; k >= 0; --k) {
                float tv = (ti >= 0) ? t[ti] : -1.f;
                float ov = (oi >= 0) ? o[oi] : -1.f;
                if (tv >= ov) { m[k] = tv; --ti; }
                else          { m[k] = ov; --oi; }
            }
#pragma unroll
            for (int i = 0; i < TOPK; ++i) { t[i] = m[i]; sv[tid * TOPK + i] = m[i]; }
        }
        __syncthreads();
    }
    if (tid == 0) g_thresh[g] = t[0];      // 10th largest (0 if fewer than 10 positives)
}

// K3: mark fg anchors (all stored candidates are > 0, so >= thresh is the top-k set).
__global__ void __launch_bounds__(TBS) k_mark() {
    const int g = blockIdx.y;
    const int c = min(g_count[g], CAP);
    const float th = g_thresh[g];
    for (int i = blockIdx.x * blockDim.x + threadIdx.x; i < c;
         i += gridDim.x * blockDim.x) {
        if (g_val[g * CAP + i] >= th) g_fg[g_anc[g * CAP + i]] = 1;
    }
}

// K4: float32 output. out[0..A) = fg_mask as 0.0/1.0, out[A..2A) = argmax idx.
__global__ void __launch_bounds__(TBS) k_final(float* __restrict__ out, int write_idx) {
    const int a = blockIdx.x * blockDim.x + threadIdx.x;
    if (a >= NA) return;
    const int fg = g_fg[a];
    out[a] = fg ? 1.0f : 0.0f;
    if (write_idx) out[NA + a] = (float)(fg ? g_best[a] : 0);
}

extern "C" void kernel_launch(void* const* d_in, const int* in_sizes, int n_in,
                              void* d_out, int out_size) {
    // Bind inputs BY ELEMENT COUNT on the host — the five sizes are pairwise
    // distinct (400000 / 1600000 / 800000 / 64 / 256), so this is ordering-proof
    // and costs zero device work (the 246us run proved binding was never the
    // failure; the single-threaded device-side sniffer was pure overhead).
    const float*  scores = nullptr;
    const float4* pboxes = nullptr;
    const float2* anc    = nullptr;
    const float4* gtb    = nullptr;
    for (int i = 0; i < n_in; ++i) {
        switch (in_sizes[i]) {
            case NA:     scores = (const float*)d_in[i];  break;
            case NA * 4: pboxes = (const float4*)d_in[i]; break;
            case NA * 2: anc    = (const float2*)d_in[i]; break;
            case NG * 4: gtb    = (const float4*)d_in[i]; break;
            default: break;   // gt_labels (NG) unused: NUM_CLASSES == 1
        }
    }
    const int write_idx = (out_size >= 2 * NA) ? 1 : 0;

    k_zero  <<<1, 64>>>();
    k_main  <<<(NA + TBS - 1) / TBS, TBS>>>(scores, pboxes, anc, gtb);
    k_thresh<<<NG, TBS>>>();
    k_mark  <<<dim3(8, NG), TBS>>>();
    k_final <<<(NA + TBS - 1) / TBS, TBS>>>((float*)d_out, write_idx);
}